// round 1
// baseline (speedup 1.0000x reference)
#include <cuda_runtime.h>
#include <cuda_bf16.h>

// Problem constants (fixed by the dataset)
#define NCLS   20
#define IMGSZ  600.0f
#define BATCH  16
#define NA     65536
#define NM     32

// Global scratch accumulators: [0]=loc_loss, [1]=cls_loss, [2]=num_pos
__device__ double g_acc[3];

__global__ void k_init() {
    if (threadIdx.x < 3) g_acc[threadIdx.x] = 0.0;
}

__device__ __forceinline__ float smooth_l1(float d) {
    float ad = fabsf(d);
    return (ad < 1.0f) ? 0.5f * d * d : ad - 0.5f;
}

// 4 anchors per thread, 256 threads/block -> 1024 anchors/block,
// 64 blocks per image, 1024 blocks total.
__global__ void __launch_bounds__(256) k_main(
    const float* __restrict__ loc_preds,   // [B, A, 4]
    const float* __restrict__ cls_preds,   // [B, A, 20]
    const float* __restrict__ iou_boxes,   // [A, 4] xywh
    const float* __restrict__ targets)     // [B*M, 6] (bid, label, cx, cy, w, h) normalized
{
    __shared__ float s_x1[NM], s_y1[NM], s_x2[NM], s_y2[NM], s_ar[NM];
    __shared__ float s_cx[NM], s_cy[NM], s_w[NM], s_h[NM];
    __shared__ int   s_lab[NM];
    __shared__ float s_red[24];

    const int tid    = threadIdx.x;
    const int b      = blockIdx.x >> 6;                       // image index
    const int base_a = ((blockIdx.x & 63) << 10) + (tid << 2); // first of 4 anchors

    // Stage this image's 32 targets into SMEM (xyxy + xywh + area + label)
    if (tid < NM) {
        const float* tr = targets + ((b << 5) + tid) * 6;
        float lab = tr[1];
        float cx = tr[2] * IMGSZ, cy = tr[3] * IMGSZ;
        float w  = tr[4] * IMGSZ, h  = tr[5] * IMGSZ;
        s_cx[tid] = cx; s_cy[tid] = cy; s_w[tid] = w; s_h[tid] = h;
        s_x1[tid] = cx - 0.5f * w; s_y1[tid] = cy - 0.5f * h;
        s_x2[tid] = cx + 0.5f * w; s_y2[tid] = cy + 0.5f * h;
        s_ar[tid] = (w + 1.0f) * (h + 1.0f);
        s_lab[tid] = (int)lab;
    }
    __syncthreads();

    // Load 4 anchors
    float ax1[4], ay1[4], ax2[4], ay2[4], aar[4];
    float acx[4], acy[4], aw[4], ah[4];
#pragma unroll
    for (int k = 0; k < 4; k++) {
        float4 v = ((const float4*)iou_boxes)[base_a + k];
        acx[k] = v.x; acy[k] = v.y; aw[k] = v.z; ah[k] = v.w;
        ax1[k] = v.x - 0.5f * v.z; ay1[k] = v.y - 0.5f * v.w;
        ax2[k] = v.x + 0.5f * v.z; ay2[k] = v.y + 0.5f * v.w;
        aar[k] = (v.z + 1.0f) * (v.w + 1.0f);
    }

    // Division-free IoU argmax over 32 targets (cross-multiplied comparison).
    float bi[4], bu[4];
    int   bm[4];
#pragma unroll
    for (int k = 0; k < 4; k++) { bi[k] = -1.0f; bu[k] = 1.0f; bm[k] = 0; }

#pragma unroll
    for (int m = 0; m < NM; m++) {
        float tx1 = s_x1[m], ty1 = s_y1[m], tx2 = s_x2[m], ty2 = s_y2[m];
        float tar = s_ar[m];
#pragma unroll
        for (int k = 0; k < 4; k++) {
            float wi = fminf(ax2[k], tx2) - fmaxf(ax1[k], tx1) + 1.0f;
            float hi = fminf(ay2[k], ty2) - fmaxf(ay1[k], ty1) + 1.0f;
            wi = fmaxf(wi, 0.0f); hi = fmaxf(hi, 0.0f);
            float inter = wi * hi;
            float u = aar[k] + tar - inter;
            // iou_new > iou_best  <=>  inter*bu > bi*u  (u, bu > 0)
            if (inter * bu[k] > bi[k] * u) { bi[k] = inter; bu[k] = u; bm[k] = m; }
        }
    }

    float loc_acc = 0.0f, cls_acc = 0.0f, posf = 0.0f;

#pragma unroll
    for (int k = 0; k < 4; k++) {
        float max_iou = bi[k] / bu[k];
        int m = bm[k];
        int ct;
        if (max_iou < 0.5f) ct = 0; else ct = 1 + s_lab[m];
        if (max_iou > 0.4f && max_iou < 0.5f) ct = -1;

        size_t idx = (size_t)b * NA + (size_t)(base_a + k);

        if (ct > 0) {
            posf += 1.0f;
            float4 lp = ((const float4*)loc_preds)[idx];
            float invw = __fdividef(1.0f, aw[k]);
            float invh = __fdividef(1.0f, ah[k]);
            float tx = (s_cx[m] - acx[k]) * invw;
            float ty = (s_cy[m] - acy[k]) * invh;
            float tw = __logf(s_w[m] * invw);
            float th = __logf(s_h[m] * invh);
            loc_acc += smooth_l1(lp.x - tx);
            loc_acc += smooth_l1(lp.y - ty);
            loc_acc += smooth_l1(lp.z - tw);
            loc_acc += smooth_l1(lp.w - th);
        }

        if (ct > -1) {
            int pc = ct - 1;  // positive class index, or -1 if background
            const float* cp = cls_preds + idx * NCLS;
#pragma unroll
            for (int v = 0; v < 5; v++) {
                float4 q = ((const float4*)cp)[v];
                float xs[4] = {q.x, q.y, q.z, q.w};
#pragma unroll
                for (int j = 0; j < 4; j++) {
                    int c = v * 4 + j;
                    float x = xs[j];
                    float e = __expf(-x);
                    float p = __fdividef(1.0f, 1.0f + e);  // sigmoid
                    bool t = (c == pc);
                    float pt = t ? p : 1.0f - p;
                    float om = t ? 1.0f - p : p;           // 1 - pt
                    float bce = -__logf(pt);
                    cls_acc += (t ? 0.25f : 0.75f) * om * om * bce;
                }
            }
        }
    }

    // Block reduction: warp shuffles, then 8-warp SMEM combine, 3 double atomics.
#pragma unroll
    for (int o = 16; o; o >>= 1) {
        loc_acc += __shfl_down_sync(0xffffffffu, loc_acc, o);
        cls_acc += __shfl_down_sync(0xffffffffu, cls_acc, o);
        posf    += __shfl_down_sync(0xffffffffu, posf, o);
    }
    int wid = tid >> 5, lane = tid & 31;
    if (lane == 0) {
        s_red[wid]      = loc_acc;
        s_red[8 + wid]  = cls_acc;
        s_red[16 + wid] = posf;
    }
    __syncthreads();
    if (tid == 0) {
        float a0 = 0.0f, a1 = 0.0f, a2 = 0.0f;
#pragma unroll
        for (int i = 0; i < 8; i++) {
            a0 += s_red[i]; a1 += s_red[8 + i]; a2 += s_red[16 + i];
        }
        atomicAdd(&g_acc[0], (double)a0);
        atomicAdd(&g_acc[1], (double)a1);
        atomicAdd(&g_acc[2], (double)a2);
    }
}

__global__ void k_fin(float* __restrict__ out) {
    double np  = g_acc[2];
    if (np < 1.0) np = 1.0;
    double loc = g_acc[0], cls = g_acc[1];
    out[0] = (float)((loc + cls) / np);
    out[1] = (float)(loc / np);
    out[2] = (float)(cls / np);
}

extern "C" void kernel_launch(void* const* d_in, const int* in_sizes, int n_in,
                              void* d_out, int out_size) {
    const float* loc_preds = (const float*)d_in[0];
    const float* cls_preds = (const float*)d_in[1];
    const float* iou_boxes = (const float*)d_in[2];
    const float* targets   = (const float*)d_in[3];
    float* out = (float*)d_out;

    k_init<<<1, 32>>>();
    k_main<<<BATCH * (NA / 1024), 256>>>(loc_preds, cls_preds, iou_boxes, targets);
    k_fin<<<1, 1>>>(out);
}